// round 2
// baseline (speedup 1.0000x reference)
#include <cuda_runtime.h>

// Unfold (im2col) for x:(B=16, C=128, H=64, W=64), k=3, pad=1.
// out[b, c*9 + p, h*W + w] = x[b, c, h+dh-1, w+dw-1] (zero-padded), p = dh*3+dw.
// Pure bandwidth problem: 302 MB write, ~34 MB effective DRAM read (input fits L2).

#define B_ 16
#define C_ 128
#define H_ 64
#define W_ 64
#define PLANE (H_ * W_)   // 4096

__global__ __launch_bounds__(256) void unfold_kernel(
    const float* __restrict__ x, float* __restrict__ out)
{
    int idx = blockIdx.x * blockDim.x + threadIdx.x;
    // Each thread handles 4 consecutive w of one (b, c, h) row.
    // idx layout: [bc (11b)] [h (6b)] [wg (4b)]
    const int total = B_ * C_ * H_ * (W_ / 4);   // 2,097,152
    if (idx >= total) return;

    int wg = idx & 15;           // w-group 0..15
    int h  = (idx >> 4) & 63;    // 0..63
    int bc = idx >> 10;          // b*C + c, 0..2047
    int w0 = wg << 2;            // 0,4,...,60

    const float* plane = x + (size_t)bc * PLANE;

    // Load 3x6 halo window (rows h-1..h+1, cols w0-1..w0+4) with zero padding.
    float v[3][6];
#pragma unroll
    for (int r = 0; r < 3; r++) {
        int hh = h + r - 1;
        bool hok = (hh >= 0) && (hh < H_);
        const float* row = plane + hh * W_;
#pragma unroll
        for (int c = 0; c < 6; c++) {
            int ww = w0 + c - 1;
            bool ok = hok && (ww >= 0) && (ww < W_);
            v[r][c] = ok ? row[ww] : 0.0f;
        }
    }

    // 9 coalesced float4 stores, one per kernel position.
    float* outp = out + (size_t)bc * 9 * PLANE + h * W_ + w0;
#pragma unroll
    for (int p = 0; p < 9; p++) {
        int r  = p / 3;
        int cc = p % 3;
        float4 o = make_float4(v[r][cc], v[r][cc + 1], v[r][cc + 2], v[r][cc + 3]);
        *reinterpret_cast<float4*>(outp + (size_t)p * PLANE) = o;
    }
}

extern "C" void kernel_launch(void* const* d_in, const int* in_sizes, int n_in,
                              void* d_out, int out_size)
{
    const float* x = (const float*)d_in[0];
    // d_in[1] is the identity "weights" buffer — unused (it's eye(9) by construction).
    float* out = (float*)d_out;

    const int total  = B_ * C_ * H_ * (W_ / 4);  // 2,097,152 threads
    const int tpb    = 256;
    const int blocks = (total + tpb - 1) / tpb;  // 8192
    unfold_kernel<<<blocks, tpb>>>(x, out);
}